// round 2
// baseline (speedup 1.0000x reference)
#include <cuda_runtime.h>
#include <cuda_bf16.h>

#define B_ 8
#define C_ 128
#define D_ 64
#define H_ 32
#define W_ 32
#define S_ 64
#define N_ (B_*H_*W_)          /* 8192 */
#define HW_ (H_*W_)            /* 1024 */
#define DHW_ (D_*HW_)          /* 65536 */
#define CD_ (C_*D_)            /* 8192 */
#define EPS_ 1e-5f

typedef unsigned long long ull;

// ---------------- device-global scratch (no runtime allocation) ----------------
__device__ __align__(16) float g_scale[C_];
__device__ __align__(16) float g_shift[C_];
__device__ __align__(16) float g_W3[C_*192];          // [c][s'] : s'<64 0.125*Wk ; <128 Wq ; <192 Wv
__device__ __align__(16) float g_WoT[S_*C_];          // [s][o]
__device__ __align__(16) float g_xt[(size_t)N_*CD_];  // 256 MB  xn transposed [n][c][d]
__device__ __align__(16) float g_ot[(size_t)N_*CD_];  // 256 MB  out-proj     [n][c][d]

// ---------------- packed f32x2 helpers ----------------
__device__ __forceinline__ void fma2(ull &d, ull a, ull b) {
    asm("fma.rn.f32x2 %0, %1, %2, %0;" : "+l"(d) : "l"(a), "l"(b));
}
__device__ __forceinline__ ull dup2(float v) {
    ull r; asm("mov.b64 %0, {%1, %1};" : "=l"(r) : "f"(v)); return r;
}
__device__ __forceinline__ float2 unpk(ull u) {
    float2 f; asm("mov.b64 {%0, %1}, %2;" : "=f"(f.x), "=f"(f.y) : "l"(u)); return f;
}
union LD4 { float4 v; ull u2[2]; float f[4]; };

// ================= K1: BN statistics =================
__global__ __launch_bounds__(1024) void k_bn(const float* __restrict__ x,
                                             const float* __restrict__ gamma,
                                             const float* __restrict__ beta) {
    __shared__ float r1[1024];
    __shared__ float r2[1024];
    const int c = blockIdx.x, t = threadIdx.x;
    float s1 = 0.f, s2 = 0.f;
    for (int b = 0; b < B_; b++) {
        const float4* p = (const float4*)(x + ((size_t)b*C_ + c)*DHW_);
        #pragma unroll 4
        for (int j = 0; j < 16; j++) {
            float4 v = p[t + j*1024];
            s1 += v.x + v.y + v.z + v.w;
            s2 += v.x*v.x + v.y*v.y + v.z*v.z + v.w*v.w;
        }
    }
    r1[t] = s1; r2[t] = s2;
    __syncthreads();
    for (int st = 512; st > 0; st >>= 1) {
        if (t < st) { r1[t] += r1[t+st]; r2[t] += r2[t+st]; }
        __syncthreads();
    }
    if (t == 0) {
        const float inv = 1.f / (float)(B_*DHW_);
        float mean = r1[0]*inv;
        float var  = r2[0]*inv - mean*mean;
        float sc = gamma[c] * rsqrtf(var + EPS_);
        g_scale[c] = sc;
        g_shift[c] = beta[c] - mean*sc;
    }
}

// ================= K2: weight prep =================
__global__ __launch_bounds__(256) void k_prep_w(const float* __restrict__ Wk,
                                                const float* __restrict__ Wq,
                                                const float* __restrict__ Wv,
                                                const float* __restrict__ Wo) {
    int idx = blockIdx.x*256 + threadIdx.x;  // 0..32767
    if (idx < C_*192) {
        int c = idx / 192, s = idx % 192;
        float v;
        if (s < 64)       v = 0.125f * Wk[s*C_ + c];
        else if (s < 128) v = Wq[(s-64)*C_ + c];
        else              v = Wv[(s-128)*C_ + c];
        g_W3[idx] = v;
    } else {
        int i = idx - C_*192;           // [s][o]
        int s = i >> 7, o = i & 127;
        g_WoT[i] = Wo[o*S_ + s];
    }
}

// ================= K3: transpose-in + BN apply =================
__global__ __launch_bounds__(256) void k_tin(const float* __restrict__ x) {
    __shared__ float tile[32*65];
    const int t = threadIdx.x, bid = blockIdx.x;
    const int b = bid >> 12, rem = bid & 4095;
    const int c = rem >> 5, h = rem & 31;
    const float sc = g_scale[c], sh = g_shift[c];
    const size_t base_x = (((size_t)b*C_ + c)*D_)*HW_ + (size_t)h*W_;
    #pragma unroll
    for (int k = 0; k < 8; k++) {
        int idx = t + k*256;
        int d = idx >> 5, w = idx & 31;
        tile[w*65 + d] = x[base_x + (size_t)d*HW_ + w]*sc + sh;
    }
    __syncthreads();
    const size_t base_t = ((size_t)(b*HW_ + h*W_))*CD_ + (size_t)c*D_;
    #pragma unroll
    for (int k = 0; k < 8; k++) {
        int idx = t + k*256;
        int w = idx >> 6, d = idx & 63;
        g_xt[base_t + (size_t)w*CD_ + d] = tile[w*65 + d];
    }
}

// ================= K4: fused attention (persistent) =================
// smem floats: W3 24576 | WoT 8192 | X 8192 (attn in [0:4096], scores in [4096:8192]) | KQV 12288 | RED 320
#define OFF_W3  0
#define OFF_WOT 24576
#define OFF_X   32768
#define OFF_SC  36864
#define OFF_KQV 40960
#define OFF_RED 53248
#define SMEM_FLOATS 53568

__global__ __launch_bounds__(256, 1) void k_attn() {
    extern __shared__ float sm[];
    float* W3s  = sm + OFF_W3;
    float* WOTs = sm + OFF_WOT;
    float* Xs   = sm + OFF_X;
    float* SCs  = sm + OFF_SC;
    float* ATs  = sm + OFF_X;      // attn result aliases lower half of X
    float* KQVs = sm + OFF_KQV;
    float* RED  = sm + OFF_RED;
    const int t = threadIdx.x;

    // -------- prologue: resident weights --------
    {
        const float4* s3 = (const float4*)g_W3;
        float4* d3 = (float4*)W3s;
        #pragma unroll
        for (int k = 0; k < 24; k++) d3[t + k*256] = s3[t + k*256];
        const float4* so = (const float4*)g_WoT;
        float4* do_ = (float4*)WOTs;
        #pragma unroll
        for (int k = 0; k < 8; k++) do_[t + k*256] = so[t + k*256];
    }
    __syncthreads();

    const int tx = t & 7, ty = t >> 3;

    for (int n = blockIdx.x; n < N_; n += gridDim.x) {
        // -------- A: load x tile --------
        {
            const float4* src = (const float4*)(g_xt + (size_t)n*CD_);
            float4* dst = (float4*)Xs;
            #pragma unroll
            for (int k = 0; k < 8; k++) dst[t + k*256] = src[t + k*256];
        }
        __syncthreads();

        // -------- B: KQV = W3 @ X  (192x64, contract C=128) --------
        {
            const int rb = ty*6, cb = tx*8;
            ull acc[6][4];
            #pragma unroll
            for (int r = 0; r < 6; r++)
                #pragma unroll
                for (int k = 0; k < 4; k++) acc[r][k] = 0ull;
            #pragma unroll 2
            for (int c = 0; c < 128; c++) {
                LD4 xa, xb;
                xa.v = *(const float4*)&Xs[c*64 + cb];
                xb.v = *(const float4*)&Xs[c*64 + cb + 4];
                const float2 wA = *(const float2*)&W3s[c*192 + rb];
                const float2 wB = *(const float2*)&W3s[c*192 + rb + 2];
                const float2 wC = *(const float2*)&W3s[c*192 + rb + 4];
                ull d0 = dup2(wA.x), d1 = dup2(wA.y), d2 = dup2(wB.x);
                ull d3 = dup2(wB.y), d4 = dup2(wC.x), d5 = dup2(wC.y);
                fma2(acc[0][0], d0, xa.u2[0]); fma2(acc[0][1], d0, xa.u2[1]); fma2(acc[0][2], d0, xb.u2[0]); fma2(acc[0][3], d0, xb.u2[1]);
                fma2(acc[1][0], d1, xa.u2[0]); fma2(acc[1][1], d1, xa.u2[1]); fma2(acc[1][2], d1, xb.u2[0]); fma2(acc[1][3], d1, xb.u2[1]);
                fma2(acc[2][0], d2, xa.u2[0]); fma2(acc[2][1], d2, xa.u2[1]); fma2(acc[2][2], d2, xb.u2[0]); fma2(acc[2][3], d2, xb.u2[1]);
                fma2(acc[3][0], d3, xa.u2[0]); fma2(acc[3][1], d3, xa.u2[1]); fma2(acc[3][2], d3, xb.u2[0]); fma2(acc[3][3], d3, xb.u2[1]);
                fma2(acc[4][0], d4, xa.u2[0]); fma2(acc[4][1], d4, xa.u2[1]); fma2(acc[4][2], d4, xb.u2[0]); fma2(acc[4][3], d4, xb.u2[1]);
                fma2(acc[5][0], d5, xa.u2[0]); fma2(acc[5][1], d5, xa.u2[1]); fma2(acc[5][2], d5, xb.u2[0]); fma2(acc[5][3], d5, xb.u2[1]);
            }
            #pragma unroll
            for (int r = 0; r < 6; r++)
                #pragma unroll
                for (int k = 0; k < 4; k++)
                    *(float2*)&KQVs[(rb + r)*64 + cb + 2*k] = unpk(acc[r][k]);
        }
        __syncthreads();

        // -------- C: scores[i][j] = sum_s K[s][i]*Q[s][j]  (K pre-scaled by 1/8) --------
        if (t < 128) {
            const int ctx = t & 7, cty = t >> 3;   // 16 row groups
            const int ib = cty*4, jb = ctx*8;
            ull acc[4][4];
            #pragma unroll
            for (int r = 0; r < 4; r++)
                #pragma unroll
                for (int k = 0; k < 4; k++) acc[r][k] = 0ull;
            #pragma unroll 2
            for (int s = 0; s < 64; s++) {
                LD4 kv, qa, qb;
                kv.v = *(const float4*)&KQVs[s*64 + ib];
                qa.v = *(const float4*)&KQVs[(64 + s)*64 + jb];
                qb.v = *(const float4*)&KQVs[(64 + s)*64 + jb + 4];
                #pragma unroll
                for (int r = 0; r < 4; r++) {
                    ull d = dup2(kv.f[r]);
                    fma2(acc[r][0], d, qa.u2[0]); fma2(acc[r][1], d, qa.u2[1]);
                    fma2(acc[r][2], d, qb.u2[0]); fma2(acc[r][3], d, qb.u2[1]);
                }
            }
            #pragma unroll
            for (int r = 0; r < 4; r++)
                #pragma unroll
                for (int k = 0; k < 4; k++)
                    *(float2*)&SCs[(ib + r)*64 + jb + 2*k] = unpk(acc[r][k]);
        }
        __syncthreads();

        // -------- softmax over i (columns of SCs) --------
        {
            const int j = t & 63, qq = t >> 6;
            const int i0 = qq*16;
            float m = -1e30f;
            #pragma unroll 4
            for (int ii = 0; ii < 16; ii++) m = fmaxf(m, SCs[(i0 + ii)*64 + j]);
            RED[t] = m;
            __syncthreads();
            const float m4 = fmaxf(fmaxf(RED[j], RED[64 + j]), fmaxf(RED[128 + j], RED[192 + j]));
            float ssum = 0.f;
            #pragma unroll 4
            for (int ii = 0; ii < 16; ii++) {
                float e = __expf(SCs[(i0 + ii)*64 + j] - m4);
                SCs[(i0 + ii)*64 + j] = e;
                ssum += e;
            }
            __syncthreads();           // RED max values consumed by all before overwrite
            RED[t] = ssum;
            __syncthreads();
            const float inv = 1.f / (RED[j] + RED[64 + j] + RED[128 + j] + RED[192 + j]);
            #pragma unroll 4
            for (int ii = 0; ii < 16; ii++) SCs[(i0 + ii)*64 + j] *= inv;
        }
        __syncthreads();

        // -------- D: attn[s][j] = sum_i V[s][i]*A[i][j] --------
        if (t < 128) {
            const int ctx = t & 7, cty = t >> 3;
            const int sb = cty*4, jb = ctx*8;
            ull acc[4][4];
            #pragma unroll
            for (int r = 0; r < 4; r++)
                #pragma unroll
                for (int k = 0; k < 4; k++) acc[r][k] = 0ull;
            #pragma unroll 2
            for (int i = 0; i < 64; i++) {
                const float v0 = KQVs[(128 + sb + 0)*64 + i];
                const float v1 = KQVs[(128 + sb + 1)*64 + i];
                const float v2 = KQVs[(128 + sb + 2)*64 + i];
                const float v3 = KQVs[(128 + sb + 3)*64 + i];
                LD4 aa, ab;
                aa.v = *(const float4*)&SCs[i*64 + jb];
                ab.v = *(const float4*)&SCs[i*64 + jb + 4];
                ull d0 = dup2(v0), d1 = dup2(v1), d2 = dup2(v2), d3 = dup2(v3);
                fma2(acc[0][0], d0, aa.u2[0]); fma2(acc[0][1], d0, aa.u2[1]); fma2(acc[0][2], d0, ab.u2[0]); fma2(acc[0][3], d0, ab.u2[1]);
                fma2(acc[1][0], d1, aa.u2[0]); fma2(acc[1][1], d1, aa.u2[1]); fma2(acc[1][2], d1, ab.u2[0]); fma2(acc[1][3], d1, ab.u2[1]);
                fma2(acc[2][0], d2, aa.u2[0]); fma2(acc[2][1], d2, aa.u2[1]); fma2(acc[2][2], d2, ab.u2[0]); fma2(acc[2][3], d2, ab.u2[1]);
                fma2(acc[3][0], d3, aa.u2[0]); fma2(acc[3][1], d3, aa.u2[1]); fma2(acc[3][2], d3, ab.u2[0]); fma2(acc[3][3], d3, ab.u2[1]);
            }
            #pragma unroll
            for (int r = 0; r < 4; r++)
                #pragma unroll
                for (int k = 0; k < 4; k++)
                    *(float2*)&ATs[(sb + r)*64 + jb + 2*k] = unpk(acc[r][k]);
        }
        __syncthreads();

        // -------- E: out[o][d] = sum_s WoT[s][o]*attn[s][d] --------
        {
            const int ob = ty*4, db = tx*8;
            ull acc[4][4];
            #pragma unroll
            for (int r = 0; r < 4; r++)
                #pragma unroll
                for (int k = 0; k < 4; k++) acc[r][k] = 0ull;
            #pragma unroll 2
            for (int s = 0; s < 64; s++) {
                LD4 wo, aa, ab;
                wo.v = *(const float4*)&WOTs[s*128 + ob];
                aa.v = *(const float4*)&ATs[s*64 + db];
                ab.v = *(const float4*)&ATs[s*64 + db + 4];
                #pragma unroll
                for (int r = 0; r < 4; r++) {
                    ull d = dup2(wo.f[r]);
                    fma2(acc[r][0], d, aa.u2[0]); fma2(acc[r][1], d, aa.u2[1]);
                    fma2(acc[r][2], d, ab.u2[0]); fma2(acc[r][3], d, ab.u2[1]);
                }
            }
            float* dst = g_ot + (size_t)n*CD_;
            #pragma unroll
            for (int r = 0; r < 4; r++) {
                LD4 o1, o2;
                o1.u2[0] = acc[r][0]; o1.u2[1] = acc[r][1];
                o2.u2[0] = acc[r][2]; o2.u2[1] = acc[r][3];
                *(float4*)&dst[(ob + r)*64 + db]     = o1.v;
                *(float4*)&dst[(ob + r)*64 + db + 4] = o2.v;
            }
        }
        __syncthreads();   // Xs/KQVs reused next iteration
    }
}

// ================= K5: transpose-out + residual =================
__global__ __launch_bounds__(256) void k_tout(const float* __restrict__ x,
                                              float* __restrict__ out) {
    __shared__ float tile[32*65];
    const int t = threadIdx.x, bid = blockIdx.x;
    const int b = bid >> 12, rem = bid & 4095;
    const int c = rem >> 5, h = rem & 31;
    const size_t base_t = ((size_t)(b*HW_ + h*W_))*CD_ + (size_t)c*D_;
    #pragma unroll
    for (int k = 0; k < 8; k++) {
        int idx = t + k*256;
        int w = idx >> 6, d = idx & 63;
        tile[w*65 + d] = g_ot[base_t + (size_t)w*CD_ + d];
    }
    __syncthreads();
    const size_t base_x = (((size_t)b*C_ + c)*D_)*HW_ + (size_t)h*W_;
    #pragma unroll
    for (int k = 0; k < 8; k++) {
        int idx = t + k*256;
        int d = idx >> 5, w = idx & 31;
        size_t g = base_x + (size_t)d*HW_ + w;
        out[g] = x[g] + tile[w*65 + d];
    }
}

// ================= launch =================
extern "C" void kernel_launch(void* const* d_in, const int* in_sizes, int n_in,
                              void* d_out, int out_size) {
    const float* x     = (const float*)d_in[0];
    const float* Wk    = (const float*)d_in[1];
    const float* Wq    = (const float*)d_in[2];
    const float* Wv    = (const float*)d_in[3];
    const float* Wo    = (const float*)d_in[4];
    const float* gamma = (const float*)d_in[5];
    const float* beta  = (const float*)d_in[6];
    float* out = (float*)d_out;

    static_assert(SMEM_FLOATS*4 == 214272, "smem size");
    cudaFuncSetAttribute(k_attn, cudaFuncAttributeMaxDynamicSharedMemorySize, SMEM_FLOATS*4);

    k_bn<<<C_, 1024>>>(x, gamma, beta);
    k_prep_w<<<128, 256>>>(Wk, Wq, Wv, Wo);
    k_tin<<<B_*C_*H_, 256>>>(x);
    k_attn<<<296, 256, SMEM_FLOATS*4>>>();
    k_tout<<<B_*C_*H_, 256>>>(x, out);
}

// round 4
// speedup vs baseline: 1.2178x; 1.2178x over previous
#include <cuda_runtime.h>
#include <cuda_bf16.h>

#define B_ 8
#define C_ 128
#define D_ 64
#define H_ 32
#define W_ 32
#define S_ 64
#define N_ (B_*H_*W_)          /* 8192 */
#define HW_ (H_*W_)            /* 1024 */
#define DHW_ (D_*HW_)          /* 65536 */
#define CD_ (C_*D_)            /* 8192 */
#define EPS_ 1e-5f

typedef unsigned long long ull;

// ---------------- device-global scratch ----------------
__device__ __align__(16) float g_scale[C_];
__device__ __align__(16) float g_shift[C_];
__device__ __align__(16) float g_W3[C_*192];          // [c][s'] : s'<64 0.125*Wk ; <128 Wq ; <192 Wv
__device__ __align__(16) float g_WoT[S_*C_];          // [s][o]
__device__ __align__(16) float g_xt[(size_t)N_*CD_];  // xn transposed [n][c][d]
__device__ __align__(16) float g_ot[(size_t)N_*CD_];  // out-proj     [n][o][d]

// ---------------- packed f32x2 helpers ----------------
__device__ __forceinline__ void fma2(ull &d, ull a, ull b) {
    asm("fma.rn.f32x2 %0, %1, %2, %0;" : "+l"(d) : "l"(a), "l"(b));
}
__device__ __forceinline__ ull dup2(float v) {
    ull r; asm("mov.b64 %0, {%1, %1};" : "=l"(r) : "f"(v)); return r;
}
__device__ __forceinline__ float2 unpk(ull u) {
    float2 f; asm("mov.b64 {%0, %1}, %2;" : "=f"(f.x), "=f"(f.y) : "l"(u)); return f;
}
union LD4 { float4 v; ull u2[2]; float f[4]; };

// ================= K1: BN statistics =================
__global__ __launch_bounds__(1024) void k_bn(const float* __restrict__ x,
                                             const float* __restrict__ gamma,
                                             const float* __restrict__ beta) {
    __shared__ float r1[1024];
    __shared__ float r2[1024];
    const int c = blockIdx.x, t = threadIdx.x;
    float s1 = 0.f, s2 = 0.f;
    for (int b = 0; b < B_; b++) {
        const float4* p = (const float4*)(x + ((size_t)b*C_ + c)*DHW_);
        #pragma unroll 4
        for (int j = 0; j < 16; j++) {
            float4 v = p[t + j*1024];
            s1 += v.x + v.y + v.z + v.w;
            s2 += v.x*v.x + v.y*v.y + v.z*v.z + v.w*v.w;
        }
    }
    r1[t] = s1; r2[t] = s2;
    __syncthreads();
    for (int st = 512; st > 0; st >>= 1) {
        if (t < st) { r1[t] += r1[t+st]; r2[t] += r2[t+st]; }
        __syncthreads();
    }
    if (t == 0) {
        const float inv = 1.f / (float)(B_*DHW_);
        float mean = r1[0]*inv;
        float var  = r2[0]*inv - mean*mean;
        float sc = gamma[c] * rsqrtf(var + EPS_);
        g_scale[c] = sc;
        g_shift[c] = beta[c] - mean*sc;
    }
}

// ================= K2: weight prep =================
__global__ __launch_bounds__(256) void k_prep_w(const float* __restrict__ Wk,
                                                const float* __restrict__ Wq,
                                                const float* __restrict__ Wv,
                                                const float* __restrict__ Wo) {
    int idx = blockIdx.x*256 + threadIdx.x;  // 0..32767
    if (idx < C_*192) {
        int c = idx / 192, s = idx % 192;
        float v;
        if (s < 64)       v = 0.125f * Wk[s*C_ + c];
        else if (s < 128) v = Wq[(s-64)*C_ + c];
        else              v = Wv[(s-128)*C_ + c];
        g_W3[idx] = v;
    } else {
        int i = idx - C_*192;           // [s][o]
        int s = i >> 7, o = i & 127;
        g_WoT[i] = Wo[o*S_ + s];
    }
}

// ================= K3: transpose-in + BN apply =================
__global__ __launch_bounds__(256) void k_tin(const float* __restrict__ x) {
    __shared__ float tile[32*65];
    const int t = threadIdx.x, bid = blockIdx.x;
    const int b = bid >> 12, rem = bid & 4095;
    const int c = rem >> 5, h = rem & 31;
    const float sc = g_scale[c], sh = g_shift[c];
    const size_t base_x = (((size_t)b*C_ + c)*D_)*HW_ + (size_t)h*W_;
    #pragma unroll
    for (int k = 0; k < 8; k++) {
        int idx = t + k*256;
        int d = idx >> 5, w = idx & 31;
        tile[w*65 + d] = x[base_x + (size_t)d*HW_ + w]*sc + sh;
    }
    __syncthreads();
    const size_t base_t = ((size_t)(b*HW_ + h*W_))*CD_ + (size_t)c*D_;
    #pragma unroll
    for (int k = 0; k < 8; k++) {
        int idx = t + k*256;
        int w = idx >> 6, d = idx & 63;
        g_xt[base_t + (size_t)w*CD_ + d] = tile[w*65 + d];
    }
}

// ================= K4: fused attention (persistent, 512 thr, broadcast-operand GEMMs) =================
// smem floats:
//   W3   [0      : 24576)   [c][192]
//   WoT  [24576  : 32768)   [s][128]
//   X    [32768  : 40960)   [c][64]    (SC aliases 32768..36864, AT aliases 36864..40960)
//   KQ   [40960  : 49152)   [row][64]  rows 0..63 = K, 64..127 = Q
//   VT   [49152  : 53504)   [i][68]    V transposed, padded stride
//   RED  [53504  : 54016)
#define OFF_W3  0
#define OFF_WOT 24576
#define OFF_X   32768
#define OFF_SC  32768
#define OFF_AT  36864
#define OFF_KQ  40960
#define OFF_VT  49152
#define OFF_RED 53504
#define SMEM_FLOATS 54016

__global__ __launch_bounds__(512, 1) void k_attn() {
    extern __shared__ float sm[];
    float* W3s  = sm + OFF_W3;
    float* WOTs = sm + OFF_WOT;
    float* Xs   = sm + OFF_X;
    float* SCs  = sm + OFF_SC;
    float* ATs  = sm + OFF_AT;
    float* KQs  = sm + OFF_KQ;
    float* VTs  = sm + OFF_VT;
    float* RED  = sm + OFF_RED;
    const int t = threadIdx.x;
    const int w = t >> 5, lane = t & 31;

    // -------- prologue: resident weights --------
    {
        const float4* s3 = (const float4*)g_W3;
        float4* d3 = (float4*)W3s;
        #pragma unroll
        for (int k = 0; k < 12; k++) d3[t + k*512] = s3[t + k*512];
        const float4* so = (const float4*)g_WoT;
        float4* d4 = (float4*)WOTs;
        #pragma unroll
        for (int k = 0; k < 4; k++) d4[t + k*512] = so[t + k*512];
    }
    __syncthreads();

    for (int n = blockIdx.x; n < N_; n += gridDim.x) {
        // -------- A: load x tile [128][64] --------
        {
            const float4* src = (const float4*)(g_xt + (size_t)n*CD_);
            float4* dst = (float4*)Xs;
            #pragma unroll
            for (int k = 0; k < 4; k++) dst[t + k*512] = src[t + k*512];
        }
        __syncthreads();

        // -------- B: KQV = W3 @ X  (192x64 over c=128) --------
        // warp w owns output rows [12w,12w+12) (broadcast W), lane owns 2 cols.
        {
            const int rb = w*12, cb = lane*2;
            ull acc[6][2];
            #pragma unroll
            for (int p = 0; p < 6; p++) { acc[p][0] = 0ull; acc[p][1] = 0ull; }
            const float* wp = W3s + rb;
            const float* xp = Xs + cb;
            #pragma unroll 4
            for (int c = 0; c < 128; c++) {
                LD4 wa, wb, wc;
                wa.v = *(const float4*)(wp + c*192);
                wb.v = *(const float4*)(wp + c*192 + 4);
                wc.v = *(const float4*)(wp + c*192 + 8);
                float2 xv = *(const float2*)(xp + c*64);
                ull x0 = dup2(xv.x), x1 = dup2(xv.y);
                fma2(acc[0][0], wa.u2[0], x0); fma2(acc[0][1], wa.u2[0], x1);
                fma2(acc[1][0], wa.u2[1], x0); fma2(acc[1][1], wa.u2[1], x1);
                fma2(acc[2][0], wb.u2[0], x0); fma2(acc[2][1], wb.u2[0], x1);
                fma2(acc[3][0], wb.u2[1], x0); fma2(acc[3][1], wb.u2[1], x1);
                fma2(acc[4][0], wc.u2[0], x0); fma2(acc[4][1], wc.u2[0], x1);
                fma2(acc[5][0], wc.u2[1], x0); fma2(acc[5][1], wc.u2[1], x1);
            }
            #pragma unroll
            for (int p = 0; p < 6; p++) {
                const int row = rb + 2*p;
                float2 va = unpk(acc[p][0]);   // (row, row+1) at col cb
                float2 vb = unpk(acc[p][1]);   // (row, row+1) at col cb+1
                if (row < 128) {               // warp-uniform branch
                    *(float2*)&KQs[row*64 + cb]     = make_float2(va.x, vb.x);
                    *(float2*)&KQs[(row+1)*64 + cb] = make_float2(va.y, vb.y);
                } else {                        // V -> transposed [i][68]
                    *(float2*)&VTs[cb*68     + (row-128)] = va;
                    *(float2*)&VTs[(cb+1)*68 + (row-128)] = vb;
                }
            }
        }
        __syncthreads();

        // -------- C: scores[i][j] = sum_s K[s][i]*Q[s][j]  (K pre-scaled 1/8) --------
        // warp w owns i-block [4w,4w+4) (broadcast K), lane owns 2 j-cols.
        {
            const int ib = w*4, jb = lane*2;
            ull acc[2][2];
            acc[0][0]=0ull; acc[0][1]=0ull; acc[1][0]=0ull; acc[1][1]=0ull;
            #pragma unroll 4
            for (int s = 0; s < 64; s++) {
                LD4 kv; kv.v = *(const float4*)&KQs[s*64 + ib];
                float2 qv = *(const float2*)&KQs[(64+s)*64 + jb];
                ull q0 = dup2(qv.x), q1 = dup2(qv.y);
                fma2(acc[0][0], kv.u2[0], q0); fma2(acc[0][1], kv.u2[0], q1);
                fma2(acc[1][0], kv.u2[1], q0); fma2(acc[1][1], kv.u2[1], q1);
            }
            #pragma unroll
            for (int p = 0; p < 2; p++) {
                float2 va = unpk(acc[p][0]);
                float2 vb = unpk(acc[p][1]);
                *(float2*)&SCs[(ib+2*p)*64 + jb]   = make_float2(va.x, vb.x);
                *(float2*)&SCs[(ib+2*p+1)*64 + jb] = make_float2(va.y, vb.y);
            }
        }
        __syncthreads();

        // -------- softmax over i (columns) --------
        {
            const int j = t & 63, g = t >> 6;   // g in 0..7, rows 8g..8g+7
            float m = -1e30f;
            #pragma unroll
            for (int r = 0; r < 8; r++) m = fmaxf(m, SCs[(g*8+r)*64 + j]);
            RED[t] = m;
            __syncthreads();
            float mm = RED[j];
            #pragma unroll
            for (int g2 = 1; g2 < 8; g2++) mm = fmaxf(mm, RED[g2*64 + j]);
            float ss = 0.f;
            #pragma unroll
            for (int r = 0; r < 8; r++) {
                float e = __expf(SCs[(g*8+r)*64 + j] - mm);
                SCs[(g*8+r)*64 + j] = e;
                ss += e;
            }
            __syncthreads();
            RED[t] = ss;
            __syncthreads();
            float tot = RED[j];
            #pragma unroll
            for (int g2 = 1; g2 < 8; g2++) tot += RED[g2*64 + j];
            const float inv = 1.f / tot;
            #pragma unroll
            for (int r = 0; r < 8; r++) SCs[(g*8+r)*64 + j] *= inv;
        }
        __syncthreads();

        // -------- D: attn[s][j] = sum_i V[s][i]*A[i][j] --------
        // warp w owns s-block [4w,4w+4) (broadcast VT), lane owns 2 j-cols.
        {
            const int sb = w*4, jb = lane*2;
            ull acc[2][2];
            acc[0][0]=0ull; acc[0][1]=0ull; acc[1][0]=0ull; acc[1][1]=0ull;
            #pragma unroll 4
            for (int i = 0; i < 64; i++) {
                LD4 vv; vv.v = *(const float4*)&VTs[i*68 + sb];
                float2 av = *(const float2*)&SCs[i*64 + jb];
                ull a0 = dup2(av.x), a1 = dup2(av.y);
                fma2(acc[0][0], vv.u2[0], a0); fma2(acc[0][1], vv.u2[0], a1);
                fma2(acc[1][0], vv.u2[1], a0); fma2(acc[1][1], vv.u2[1], a1);
            }
            #pragma unroll
            for (int p = 0; p < 2; p++) {
                float2 va = unpk(acc[p][0]);
                float2 vb = unpk(acc[p][1]);
                *(float2*)&ATs[(sb+2*p)*64 + jb]   = make_float2(va.x, vb.x);
                *(float2*)&ATs[(sb+2*p+1)*64 + jb] = make_float2(va.y, vb.y);
            }
        }
        __syncthreads();

        // -------- E: out[o][d] = sum_s WoT[s][o]*attn[s][d] --------
        // warp w owns o-block [8w,8w+8) (broadcast WoT), lane owns 2 d-cols.
        {
            const int ob = w*8, db = lane*2;
            ull acc[4][2];
            #pragma unroll
            for (int p = 0; p < 4; p++) { acc[p][0] = 0ull; acc[p][1] = 0ull; }
            #pragma unroll 4
            for (int s = 0; s < 64; s++) {
                LD4 w1, w2;
                w1.v = *(const float4*)&WOTs[s*128 + ob];
                w2.v = *(const float4*)&WOTs[s*128 + ob + 4];
                float2 av = *(const float2*)&ATs[s*64 + db];
                ull a0 = dup2(av.x), a1 = dup2(av.y);
                fma2(acc[0][0], w1.u2[0], a0); fma2(acc[0][1], w1.u2[0], a1);
                fma2(acc[1][0], w1.u2[1], a0); fma2(acc[1][1], w1.u2[1], a1);
                fma2(acc[2][0], w2.u2[0], a0); fma2(acc[2][1], w2.u2[0], a1);
                fma2(acc[3][0], w2.u2[1], a0); fma2(acc[3][1], w2.u2[1], a1);
            }
            float* dst = g_ot + (size_t)n*CD_;
            #pragma unroll
            for (int p = 0; p < 4; p++) {
                float2 va = unpk(acc[p][0]);
                float2 vb = unpk(acc[p][1]);
                *(float2*)&dst[(ob+2*p)*64 + db]   = make_float2(va.x, vb.x);
                *(float2*)&dst[(ob+2*p+1)*64 + db] = make_float2(va.y, vb.y);
            }
        }
        __syncthreads();   // smem reused next iteration
    }
}

// ================= K5: transpose-out + residual =================
__global__ __launch_bounds__(256) void k_tout(const float* __restrict__ x,
                                              float* __restrict__ out) {
    __shared__ float tile[32*65];
    const int t = threadIdx.x, bid = blockIdx.x;
    const int b = bid >> 12, rem = bid & 4095;
    const int c = rem >> 5, h = rem & 31;
    const size_t base_t = ((size_t)(b*HW_ + h*W_))*CD_ + (size_t)c*D_;
    #pragma unroll
    for (int k = 0; k < 8; k++) {
        int idx = t + k*256;
        int w = idx >> 6, d = idx & 63;
        tile[w*65 + d] = g_ot[base_t + (size_t)w*CD_ + d];
    }
    __syncthreads();
    const size_t base_x = (((size_t)b*C_ + c)*D_)*HW_ + (size_t)h*W_;
    #pragma unroll
    for (int k = 0; k < 8; k++) {
        int idx = t + k*256;
        int d = idx >> 5, w = idx & 31;
        size_t g = base_x + (size_t)d*HW_ + w;
        out[g] = x[g] + tile[w*65 + d];
    }
}

// ================= launch =================
extern "C" void kernel_launch(void* const* d_in, const int* in_sizes, int n_in,
                              void* d_out, int out_size) {
    const float* x     = (const float*)d_in[0];
    const float* Wk    = (const float*)d_in[1];
    const float* Wq    = (const float*)d_in[2];
    const float* Wv    = (const float*)d_in[3];
    const float* Wo    = (const float*)d_in[4];
    const float* gamma = (const float*)d_in[5];
    const float* beta  = (const float*)d_in[6];
    float* out = (float*)d_out;

    static_assert(SMEM_FLOATS*4 == 216064, "smem size");
    cudaFuncSetAttribute(k_attn, cudaFuncAttributeMaxDynamicSharedMemorySize, SMEM_FLOATS*4);

    k_bn<<<C_, 1024>>>(x, gamma, beta);
    k_prep_w<<<128, 256>>>(Wk, Wq, Wv, Wo);
    k_tin<<<B_*C_*H_, 256>>>(x);
    k_attn<<<148, 512, SMEM_FLOATS*4>>>();
    k_tout<<<B_*C_*H_, 256>>>(x, out);
}